// round 16
// baseline (speedup 1.0000x reference)
#include <cuda_runtime.h>
#include <cstdint>

// HOG fused kernel R16: R15 body + rcp-based classification (no k*v muls)
// + f32x2 packed column sums / gx. 8-byte cp.async tile fill, stride-10 tile,
// 9-slot mod-9 histogram, paired overlapped RMW.
// x: (64,1,512,512) f32. out: (64, 9*64*64) f32.
// Block = (image n, cell-row cy) stripe, 256 threads: cell = t/4, sub = t%4 (2 rows).
// Tile: col c -> 10*(c>>3) + (c&7) + 4; halos shared (10c+1 / 10c+14); pads idx 1/644.

#define TS2 646
typedef unsigned long long u64;

__device__ __forceinline__ uint32_t smem_u32(const void* p)
{
    uint32_t a;
    asm("{ .reg .u64 t; cvta.to.shared.u64 t, %1; cvt.u32.u64 %0, t; }"
        : "=r"(a) : "l"(p));
    return a;
}

__device__ __forceinline__ void cp_async8(uint32_t dst, const float* src)
{
    asm volatile("cp.async.ca.shared.global [%0], [%1], 8;" :: "r"(dst), "l"(src));
}
__device__ __forceinline__ void cp_async8_zero(uint32_t dst, const float* src)
{
    asm volatile("cp.async.ca.shared.global [%0], [%1], 8, 0;" :: "r"(dst), "l"(src));
}

// ---- f32x2 packed helpers (operands are aligned SASS register pairs) ----
__device__ __forceinline__ u64 fma2(u64 a, u64 b, u64 c)
{
    u64 d; asm("fma.rn.f32x2 %0, %1, %2, %3;" : "=l"(d) : "l"(a), "l"(b), "l"(c)); return d;
}
__device__ __forceinline__ u64 add2(u64 a, u64 b)
{
    u64 d; asm("add.rn.f32x2 %0, %1, %2;" : "=l"(d) : "l"(a), "l"(b)); return d;
}
__device__ __forceinline__ float2 u2f(u64 v)
{
    float2 r; asm("mov.b64 {%0, %1}, %2;" : "=f"(r.x), "=f"(r.y) : "l"(v)); return r;
}

__device__ __forceinline__ float setge(float a, float b)
{
    float r;
    asm("set.ge.f32.f32 %0, %1, %2;" : "=f"(r) : "f"(a), "f"(b));
    return r;
}

// 9-slot histogram bucket address; slot = |fa - (signs_differ ? 8 : 0)| = fl mod 9.
// Boundary tests via t = |gx|*rcp(|gy|) against constant tangents (FSET-imm).
// v=0 -> t=inf -> fa=4 (correct); u=v=0 -> t=NaN -> fa=0, mag=0 (harmless).
__device__ __forceinline__ uint32_t hog_class(float gx, float gy, uint32_t hb, float& mag)
{
    float d2 = fmaf(gx, gx, gy * gy);
    asm("sqrt.approx.f32 %0, %1;" : "=f"(mag) : "f"(d2));

    float r;
    float v = fabsf(gy);
    asm("rcp.approx.f32 %0, %1;" : "=f"(r) : "f"(v));
    float t = fabsf(gx) * r;
    float fa = (setge(t, 0.36397023f) + setge(t, 0.83909963f))
             + (setge(t, 1.73205081f) + setge(t, 5.67128182f));   // tan20,40,60,80

    uint32_t xo = __float_as_uint(gx) ^ __float_as_uint(gy);
    float cf8 = ((int)xo < 0) ? 8.0f : 0.0f;
    float m = fabsf(fa - cf8) + 12582912.0f;     // 0x4B400000 + slot (exact)
    return hb + (__float_as_uint(m) << 10);
}

__device__ __forceinline__ void hog_pair(uint32_t a0, float m0, uint32_t a1, float m1)
{
    float msum = m0 + m1;
    asm volatile(
        "{\n\t"
        ".reg .pred p;\n\t"
        ".reg .f32 t0, t1, v0;\n\t"
        "setp.ne.u32 p, %0, %1;\n\t"
        "selp.f32 v0, %2, %3, p;\n\t"
        "ld.shared.f32 t0, [%0];\n\t"
        "@p ld.shared.f32 t1, [%1];\n\t"
        "add.f32 t0, t0, v0;\n\t"
        "@p add.f32 t1, t1, %4;\n\t"
        "st.shared.f32 [%0], t0;\n\t"
        "@p st.shared.f32 [%1], t1;\n\t"
        "}"
        :: "r"(a0), "r"(a1), "f"(m0), "f"(msum), "f"(m1));
}

__device__ __forceinline__ void emit(uint32_t hb, float gx0, float gy0, float gx1, float gy1)
{
    float m0, m1;
    uint32_t q0 = hog_class(gx0, gy0, hb, m0);
    uint32_t q1 = hog_class(gx1, gy1, hb, m1);
    hog_pair(q0, m0, q1, m1);
}

__global__ __launch_bounds__(256, 5)
void hog_kernel(const float* __restrict__ x, float* __restrict__ out)
{
    __shared__ __align__(16) float tile[10 * TS2];
    __shared__ float hist[9 * 256];

    const int tid = threadIdx.x;
    const int n   = blockIdx.x >> 6;
    const int cy  = blockIdx.x & 63;

#pragma unroll
    for (int b = 0; b < 9; ++b) hist[b * 256 + tid] = 0.0f;

    // ---- tile fill: 10 rows x 256 8-byte chunks via cp.async ----
    const float* img  = x + (size_t)n * (512 * 512);
    const int    row0 = cy * 8 - 1;
    const uint32_t tb = smem_u32(tile);
    const int p = tid;
    const uint32_t dcol = (uint32_t)(10 * (p >> 2) + 2 * (p & 3) + 4);
#pragma unroll
    for (int i = 0; i < 10; ++i) {
        int gr = row0 + i;
        const float* src = img + (size_t)((unsigned)gr < 512u ? gr : 0) * 512 + 2 * p;
        uint32_t dst = tb + (i * TS2 + dcol) * 4;
        if ((unsigned)gr < 512u) cp_async8(dst, src);
        else                     cp_async8_zero(dst, src);
    }
    if (tid < 10) { tile[tid * TS2 + 1] = 0.f; tile[tid * TS2 + 644] = 0.f; }
    asm volatile("cp.async.commit_group;" ::: "memory");
    asm volatile("cp.async.wait_group 0;" ::: "memory");
    __syncthreads();

    // ---- mainloop: thread = cell (8 cols) x 2 rows; 2 cols per step ----
    const int cell = tid >> 2;
    const int sub  = tid & 3;
    const float* pw = &tile[(2 * sub + 0) * TS2 + 10 * cell];
    const float* pa = &tile[(2 * sub + 1) * TS2 + 10 * cell];
    const float* pb = &tile[(2 * sub + 2) * TS2 + 10 * cell];
    const float* pc = &tile[(2 * sub + 3) * TS2 + 10 * cell];
    const uint32_t hb = smem_u32(&hist[tid]);

    const u64 TWO2 = 0x4000000040000000ull;   // (2.0f, 2.0f)
    const u64 NEG2 = 0xBF800000BF800000ull;   // (-1.0f, -1.0f)

    float lw = pw[1], la = pa[1], lb = pb[1], lc = pc[1];   // col 8c-1
    u64 wq = *reinterpret_cast<const u64*>(pw + 4);         // cols (0,1)
    u64 aq = *reinterpret_cast<const u64*>(pa + 4);
    u64 bq = *reinterpret_cast<const u64*>(pb + 4);
    u64 cq = *reinterpret_cast<const u64*>(pc + 4);
    float2 wf = u2f(wq), af = u2f(aq), bf = u2f(bq), cf = u2f(cq);

    float Am1 = lw + 2.f * la + lb;                         // halo col sums
    float Bm1 = la + 2.f * lb + lc;
    u64 Ap = add2(fma2(aq, TWO2, wq), bq);                  // (A0, A1) packed
    u64 Bp = add2(fma2(bq, TWO2, aq), cq);                  // (B0, B1)
    float2 Apf = u2f(Ap), Bpf = u2f(Bp);

    // col 0
    emit(hb,
         Am1 - Apf.y, (lw + 2.f * wf.x + wf.y) - (lb + 2.f * bf.x + bf.y),
         Bm1 - Bpf.y, (la + 2.f * af.x + af.y) - (lc + 2.f * cf.x + cf.y));

    float w0 = wf.x, w1 = wf.y, a0 = af.x, a1 = af.y;
    float b0 = bf.x, b1 = bf.y, c0 = cf.x, c1 = cf.y;

#pragma unroll
    for (int k = 1; k < 4; ++k) {
        u64 wn = *reinterpret_cast<const u64*>(pw + 4 + 2 * k);   // cols (2k, 2k+1)
        u64 an = *reinterpret_cast<const u64*>(pa + 4 + 2 * k);
        u64 bn = *reinterpret_cast<const u64*>(pb + 4 + 2 * k);
        u64 cn = *reinterpret_cast<const u64*>(pc + 4 + 2 * k);
        float2 wnf = u2f(wn), anf = u2f(an), bnf = u2f(bn), cnf = u2f(cn);

        u64 An = add2(fma2(an, TWO2, wn), bn);   // (A[2k], A[2k+1])
        u64 Bn = add2(fma2(bn, TWO2, an), cn);
        u64 gxT2 = fma2(An, NEG2, Ap);           // gx for cols (2k-1, 2k)
        u64 gxB2 = fma2(Bn, NEG2, Bp);
        float2 gxT = u2f(gxT2), gxB = u2f(gxB2);

        // col 2k-1
        emit(hb,
             gxT.x, (w0 + 2.f * w1 + wnf.x) - (b0 + 2.f * b1 + bnf.x),
             gxB.x, (a0 + 2.f * a1 + anf.x) - (c0 + 2.f * c1 + cnf.x));
        // col 2k
        emit(hb,
             gxT.y, (w1 + 2.f * wnf.x + wnf.y) - (b1 + 2.f * bnf.x + bnf.y),
             gxB.y, (a1 + 2.f * anf.x + anf.y) - (c1 + 2.f * cnf.x + cnf.y));

        w0 = wnf.x; w1 = wnf.y; a0 = anf.x; a1 = anf.y;
        b0 = bnf.x; b1 = bnf.y; c0 = cnf.x; c1 = cnf.y;
        Ap = An; Bp = Bn;
    }

    // tail: col 7 with right halo col 8 (idx 10c+14)
    {
        float rw = pw[14], ra = pa[14], rb = pb[14], rc = pc[14];
        float A8 = rw + 2.f * ra + rb;
        float B8 = ra + 2.f * rb + rc;
        float2 Apf2 = u2f(Ap), Bpf2 = u2f(Bp);   // (A6, A7), (B6, B7)
        emit(hb,
             Apf2.x - A8, (w0 + 2.f * w1 + rw) - (b0 + 2.f * b1 + rb),
             Bpf2.x - B8, (a0 + 2.f * a1 + ra) - (c0 + 2.f * c1 + rc));
    }

    asm volatile("" ::: "memory");   // order fold reads after asm RMWs

    // ---- fold: bin[b] = P9[b] + P9[(b+8)%9]; shuffle-reduce 4 subs; write ----
    float P[9];
#pragma unroll
    for (int s = 0; s < 9; ++s) P[s] = hist[s * 256 + tid];
    float bin[9];
#pragma unroll
    for (int b = 0; b < 9; ++b) bin[b] = P[b] + P[(b + 8) % 9];

#pragma unroll
    for (int b = 0; b < 9; ++b) {
        bin[b] += __shfl_xor_sync(0xffffffffu, bin[b], 1);
        bin[b] += __shfl_xor_sync(0xffffffffu, bin[b], 2);
    }

    if (sub == 0) {
        float* o = out + (size_t)n * 36864 + cy * 64 + (tid >> 2);
#pragma unroll
        for (int b = 0; b < 9; ++b)
            o[(size_t)b * 4096] = bin[b] * 0.015625f;   // 1/64
    }
}

extern "C" void kernel_launch(void* const* d_in, const int* in_sizes, int n_in,
                              void* d_out, int out_size)
{
    const float* x = (const float*)d_in[0];
    float* out = (float*)d_out;
    (void)in_sizes; (void)n_in; (void)out_size;
    hog_kernel<<<4096, 256>>>(x, out);
}

// round 17
// speedup vs baseline: 1.0077x; 1.0077x over previous
#include <cuda_runtime.h>
#include <cstdint>

// HOG fused kernel R17: R15 body (stride-10 tile, 8-byte cp.async fill,
// 6 blocks/SM, 9-slot mod-9 histogram, paired overlapped RMW) with
// rcp.approx-based sector classification (FSET against immediates).
// x: (64,1,512,512) f32. out: (64, 9*64*64) f32.
// Block = (image n, cell-row cy) stripe, 256 threads: cell = t/4, sub = t%4 (2 rows).
// Tile: col c -> 10*(c>>3) + (c&7) + 4; halos shared (10c+1 / 10c+14); pads idx 1/644.

#define TS2 646

__device__ __forceinline__ uint32_t smem_u32(const void* p)
{
    uint32_t a;
    asm("{ .reg .u64 t; cvta.to.shared.u64 t, %1; cvt.u32.u64 %0, t; }"
        : "=r"(a) : "l"(p));
    return a;
}

__device__ __forceinline__ void cp_async8(uint32_t dst, const float* src)
{
    asm volatile("cp.async.ca.shared.global [%0], [%1], 8;" :: "r"(dst), "l"(src));
}
__device__ __forceinline__ void cp_async8_zero(uint32_t dst, const float* src)
{
    asm volatile("cp.async.ca.shared.global [%0], [%1], 8, 0;" :: "r"(dst), "l"(src));
}

__device__ __forceinline__ float setge(float a, float b)
{
    float r;
    asm("set.ge.f32.f32 %0, %1, %2;" : "=f"(r) : "f"(a), "f"(b));
    return r;
}

// 9-slot histogram bucket address; slot = |fa - (signs_differ ? 8 : 0)| = fl mod 9.
// Boundary tests via t = |gx| * rcp(|gy|) vs constant tangents (FSET-imm, MUFU pipe).
// gy=0 -> t=inf -> fa=4 (correct); gx=gy=0 -> t=NaN -> fa=0, mag=0 (harmless).
__device__ __forceinline__ uint32_t hog_class(float gx, float gy, uint32_t hb, float& mag)
{
    float d2 = fmaf(gx, gx, gy * gy);
    asm("sqrt.approx.f32 %0, %1;" : "=f"(mag) : "f"(d2));

    float r, v = fabsf(gy);
    asm("rcp.approx.f32 %0, %1;" : "=f"(r) : "f"(v));
    float t = fabsf(gx) * r;
    float fa = (setge(t, 0.36397023f) + setge(t, 0.83909963f))
             + (setge(t, 1.73205081f) + setge(t, 5.67128182f));   // tan20,40,60,80

    uint32_t xo = __float_as_uint(gx) ^ __float_as_uint(gy);
    float cf8 = ((int)xo < 0) ? 8.0f : 0.0f;
    float m = fabsf(fa - cf8) + 12582912.0f;     // 0x4B400000 + slot (exact)
    return hb + (__float_as_uint(m) << 10);
}

__device__ __forceinline__ void hog_pair(uint32_t a0, float m0, uint32_t a1, float m1)
{
    float msum = m0 + m1;
    asm volatile(
        "{\n\t"
        ".reg .pred p;\n\t"
        ".reg .f32 t0, t1, v0;\n\t"
        "setp.ne.u32 p, %0, %1;\n\t"
        "selp.f32 v0, %2, %3, p;\n\t"
        "ld.shared.f32 t0, [%0];\n\t"
        "@p ld.shared.f32 t1, [%1];\n\t"
        "add.f32 t0, t0, v0;\n\t"
        "@p add.f32 t1, t1, %4;\n\t"
        "st.shared.f32 [%0], t0;\n\t"
        "@p st.shared.f32 [%1], t1;\n\t"
        "}"
        :: "r"(a0), "r"(a1), "f"(m0), "f"(msum), "f"(m1));
}

__device__ __forceinline__ void emit(uint32_t hb, float gx0, float gy0, float gx1, float gy1)
{
    float m0, m1;
    uint32_t q0 = hog_class(gx0, gy0, hb, m0);
    uint32_t q1 = hog_class(gx1, gy1, hb, m1);
    hog_pair(q0, m0, q1, m1);
}

__global__ __launch_bounds__(256, 6)
void hog_kernel(const float* __restrict__ x, float* __restrict__ out)
{
    __shared__ __align__(16) float tile[10 * TS2];
    __shared__ float hist[9 * 256];

    const int tid = threadIdx.x;
    const int n   = blockIdx.x >> 6;
    const int cy  = blockIdx.x & 63;

#pragma unroll
    for (int b = 0; b < 9; ++b) hist[b * 256 + tid] = 0.0f;

    // ---- tile fill: 10 rows x 256 8-byte chunks via cp.async ----
    const float* img  = x + (size_t)n * (512 * 512);
    const int    row0 = cy * 8 - 1;
    const uint32_t tb = smem_u32(tile);
    const int p = tid;
    const uint32_t dcol = (uint32_t)(10 * (p >> 2) + 2 * (p & 3) + 4);
#pragma unroll
    for (int i = 0; i < 10; ++i) {
        int gr = row0 + i;
        const float* src = img + (size_t)((unsigned)gr < 512u ? gr : 0) * 512 + 2 * p;
        uint32_t dst = tb + (i * TS2 + dcol) * 4;
        if ((unsigned)gr < 512u) cp_async8(dst, src);
        else                     cp_async8_zero(dst, src);
    }
    if (tid < 10) { tile[tid * TS2 + 1] = 0.f; tile[tid * TS2 + 644] = 0.f; }
    asm volatile("cp.async.commit_group;" ::: "memory");
    asm volatile("cp.async.wait_group 0;" ::: "memory");
    __syncthreads();

    // ---- mainloop: thread = cell (8 cols) x 2 rows; 2 cols per step ----
    const int cell = tid >> 2;
    const int sub  = tid & 3;
    const float* pw = &tile[(2 * sub + 0) * TS2 + 10 * cell];
    const float* pa = &tile[(2 * sub + 1) * TS2 + 10 * cell];
    const float* pb = &tile[(2 * sub + 2) * TS2 + 10 * cell];
    const float* pc = &tile[(2 * sub + 3) * TS2 + 10 * cell];
    const uint32_t hb = smem_u32(&hist[tid]);

    float lw = pw[1], la = pa[1], lb = pb[1], lc = pc[1];   // col 8c-1
    float2 wp = *reinterpret_cast<const float2*>(pw + 4);
    float2 ap = *reinterpret_cast<const float2*>(pa + 4);
    float2 bp = *reinterpret_cast<const float2*>(pb + 4);
    float2 cp = *reinterpret_cast<const float2*>(pc + 4);

    float Am1 = lw + 2.f * la + lb;
    float Bm1 = la + 2.f * lb + lc;
    float A0 = wp.x + 2.f * ap.x + bp.x, A1 = wp.y + 2.f * ap.y + bp.y;
    float B0 = ap.x + 2.f * bp.x + cp.x, B1 = ap.y + 2.f * bp.y + cp.y;

    emit(hb,
         Am1 - A1, (lw + 2.f * wp.x + wp.y) - (lb + 2.f * bp.x + bp.y),
         Bm1 - B1, (la + 2.f * ap.x + ap.y) - (lc + 2.f * cp.x + cp.y));

    float w0 = wp.x, w1 = wp.y, a0 = ap.x, a1 = ap.y;
    float b0 = bp.x, b1 = bp.y, c0 = cp.x, c1 = cp.y;

#pragma unroll
    for (int k = 1; k < 4; ++k) {
        float2 wn = *reinterpret_cast<const float2*>(pw + 4 + 2 * k);
        float2 an = *reinterpret_cast<const float2*>(pa + 4 + 2 * k);
        float2 bn = *reinterpret_cast<const float2*>(pb + 4 + 2 * k);
        float2 cn = *reinterpret_cast<const float2*>(pc + 4 + 2 * k);
        float A2 = wn.x + 2.f * an.x + bn.x, A3 = wn.y + 2.f * an.y + bn.y;
        float B2 = an.x + 2.f * bn.x + cn.x, B3 = an.y + 2.f * bn.y + cn.y;

        emit(hb,
             A0 - A2, (w0 + 2.f * w1 + wn.x) - (b0 + 2.f * b1 + bn.x),
             B0 - B2, (a0 + 2.f * a1 + an.x) - (c0 + 2.f * c1 + cn.x));
        emit(hb,
             A1 - A3, (w1 + 2.f * wn.x + wn.y) - (b1 + 2.f * bn.x + bn.y),
             B1 - B3, (a1 + 2.f * an.x + an.y) - (c1 + 2.f * cn.x + cn.y));

        w0 = wn.x; w1 = wn.y; a0 = an.x; a1 = an.y;
        b0 = bn.x; b1 = bn.y; c0 = cn.x; c1 = cn.y;
        A0 = A2; A1 = A3; B0 = B2; B1 = B3;
    }

    // tail: col 7 with right halo col 8 (idx 10c+14)
    {
        float rw = pw[14], ra = pa[14], rb = pb[14], rc = pc[14];
        float A8 = rw + 2.f * ra + rb;
        float B8 = ra + 2.f * rb + rc;
        emit(hb,
             A0 - A8, (w0 + 2.f * w1 + rw) - (b0 + 2.f * b1 + rb),
             B0 - B8, (a0 + 2.f * a1 + ra) - (c0 + 2.f * c1 + rc));
    }

    asm volatile("" ::: "memory");   // order fold reads after asm RMWs

    // ---- fold: bin[b] = P9[b] + P9[(b+8)%9]; shuffle-reduce 4 subs; write ----
    float P[9];
#pragma unroll
    for (int s = 0; s < 9; ++s) P[s] = hist[s * 256 + tid];
    float bin[9];
#pragma unroll
    for (int b = 0; b < 9; ++b) bin[b] = P[b] + P[(b + 8) % 9];

#pragma unroll
    for (int b = 0; b < 9; ++b) {
        bin[b] += __shfl_xor_sync(0xffffffffu, bin[b], 1);
        bin[b] += __shfl_xor_sync(0xffffffffu, bin[b], 2);
    }

    if (sub == 0) {
        float* o = out + (size_t)n * 36864 + cy * 64 + cell;
#pragma unroll
        for (int b = 0; b < 9; ++b)
            o[(size_t)b * 4096] = bin[b] * 0.015625f;   // 1/64
    }
}

extern "C" void kernel_launch(void* const* d_in, const int* in_sizes, int n_in,
                              void* d_out, int out_size)
{
    const float* x = (const float*)d_in[0];
    float* out = (float*)d_out;
    (void)in_sizes; (void)n_in; (void)out_size;
    hog_kernel<<<4096, 256>>>(x, out);
}